// round 5
// baseline (speedup 1.0000x reference)
#include <cuda_runtime.h>
#include <cstdint>

#define NSEQ 512
#define DMODEL 512
#define DH 64
#define NH 8
#define KTOP 51
#define ROWS 32
#define SCALE 2.8284271247461903f   // dh^0.25

// scratch (allocation-free rule: __device__ globals)
__device__ float g_Q[NSEQ * DMODEL];
__device__ float g_K[NSEQ * DMODEL];
__device__ float g_V[NSEQ * DMODEL];
__device__ float g_ctx[NSEQ * DMODEL];
__device__ float g_qkvp[12 * NSEQ * DMODEL];  // qkv split-K partials (3 mats x 4 slices)
__device__ float g_outp[4 * NSEQ * DMODEL];   // out split-K partials (4 slices)

// ---------------------------------------------------------------------------
// cp.async helpers
// ---------------------------------------------------------------------------
__device__ __forceinline__ void cp16(uint32_t dst, const void* src) {
    asm volatile("cp.async.cg.shared.global [%0], [%1], 16;" :: "r"(dst), "l"(src));
}
__device__ __forceinline__ void cp_commit() { asm volatile("cp.async.commit_group;"); }
__device__ __forceinline__ void cp_wait1()  { asm volatile("cp.async.wait_group 1;"); }
__device__ __forceinline__ void cp_wait0()  { asm volatile("cp.async.wait_group 0;"); }

// ---------------------------------------------------------------------------
// GEMM partial: Cp(128x64 tile) = A[m, kbase:kbase+32*kiters] * B^T
// 128 threads, micro 8x8, k-in-float4 smem layout, cp.async double buffer.
// ---------------------------------------------------------------------------
#define GEMM_SMEM_F4 (2 * 8 * 129 + 2 * 8 * 65)
#define GEMM_SMEM_BYTES (GEMM_SMEM_F4 * 16)

__device__ __forceinline__ void gemm128x64(const float* __restrict__ A,
                                           const float* __restrict__ B,
                                           float* __restrict__ Cp,
                                           int kbase, int kiters)
{
    extern __shared__ float4 gsm4[];
    float4* As4 = gsm4;                 // [buf][kq*129 + m]
    float4* Bs4 = gsm4 + 2 * 8 * 129;   // [buf][kq*65 + n]
    const int t  = threadIdx.x;
    const int mr = t & 15;              // rows mr + 16*i
    const int ng = t >> 4;              // cols ng + 8*j
    const int m0 = blockIdx.y * 128;
    const int n0 = blockIdx.x * 64;

    const uint32_t sA = (uint32_t)__cvta_generic_to_shared(As4);
    const uint32_t sB = (uint32_t)__cvta_generic_to_shared(Bs4);

    auto issue = [&](int kit, int buf) {
        const int k0 = kbase + (kit << 5);
#pragma unroll
        for (int i = 0; i < 8; i++) {
            const int f = t + (i << 7);
            const int m = f >> 3, kq = f & 7;
            cp16(sA + (uint32_t)((buf * 1032 + kq * 129 + m) << 4),
                 &A[(m0 + m) * 512 + k0 + (kq << 2)]);
        }
#pragma unroll
        for (int i = 0; i < 4; i++) {
            const int f = t + (i << 7);
            const int n = f >> 3, kq = f & 7;
            cp16(sB + (uint32_t)((buf * 520 + kq * 65 + n) << 4),
                 &B[(n0 + n) * 512 + k0 + (kq << 2)]);
        }
        cp_commit();
    };

    float acc[8][8] = {};
    issue(0, 0);
    for (int kit = 0; kit < kiters; kit++) {
        const int buf = kit & 1;
        if (kit + 1 < kiters) { issue(kit + 1, buf ^ 1); cp_wait1(); }
        else                  { cp_wait0(); }
        __syncthreads();
        const float4* Ab = As4 + buf * 1032;
        const float4* Bb = Bs4 + buf * 520;
#pragma unroll
        for (int kq = 0; kq < 8; kq++) {
            float4 a4[8], b4[8];
#pragma unroll
            for (int i = 0; i < 8; i++) a4[i] = Ab[kq * 129 + mr + (i << 4)];
#pragma unroll
            for (int j = 0; j < 8; j++) b4[j] = Bb[kq * 65 + ng + (j << 3)];
#pragma unroll
            for (int i = 0; i < 8; i++)
#pragma unroll
                for (int j = 0; j < 8; j++) {
                    acc[i][j] = fmaf(a4[i].x, b4[j].x, acc[i][j]);
                    acc[i][j] = fmaf(a4[i].y, b4[j].y, acc[i][j]);
                    acc[i][j] = fmaf(a4[i].z, b4[j].z, acc[i][j]);
                    acc[i][j] = fmaf(a4[i].w, b4[j].w, acc[i][j]);
                }
        }
        __syncthreads();
    }

    // stage outputs through smem for coalesced STG.128
    float* Cs = (float*)gsm4;
#pragma unroll
    for (int i = 0; i < 8; i++)
#pragma unroll
        for (int j = 0; j < 8; j++)
            Cs[(mr + (i << 4)) * 68 + ng + (j << 3)] = acc[i][j];
    __syncthreads();
#pragma unroll
    for (int i = 0; i < 16; i++) {
        const int f = t + (i << 7);
        const int m = f >> 4, q = f & 15;
        *(float4*)&Cp[(m0 + m) * 512 + n0 + (q << 2)] =
            *(const float4*)&Cs[m * 68 + (q << 2)];
    }
}

// qkv partials: grid (8, 4, 12); z = mat*4 + kslice (K=128 per slice)
__global__ void __launch_bounds__(128) qkv_part(const float* __restrict__ X,
                                                const float* __restrict__ Wq,
                                                const float* __restrict__ Wk,
                                                const float* __restrict__ Wv)
{
    const int z = blockIdx.z;
    const int mat = z >> 2, ks = z & 3;
    const float* B = (mat == 0) ? Wq : (mat == 1) ? Wk : Wv;
    gemm128x64(X, B, g_qkvp + z * (NSEQ * DMODEL), ks << 7, 4);
}

// out partials: grid (8, 4, 4); z = kslice (K=128 per slice)
__global__ void __launch_bounds__(128) out_part(const float* __restrict__ Wo)
{
    const int ks = blockIdx.z;
    gemm128x64(g_ctx, Wo, g_outp + ks * (NSEQ * DMODEL), ks << 7, 4);
}

// reduce 4 qkv partials -> g_Q/g_K/g_V.  grid 768 x 256 (f4 granularity)
__global__ void __launch_bounds__(256) reduce_qkv()
{
    const int idx = blockIdx.x * 256 + threadIdx.x;   // 0 .. 196607
    const int mat = idx >> 16, r = idx & 0xFFFF;
    const float4* p = (const float4*)g_qkvp;
    float4 a = p[(mat * 4 + 0) * 65536 + r];
    float4 b = p[(mat * 4 + 1) * 65536 + r];
    float4 c = p[(mat * 4 + 2) * 65536 + r];
    float4 d = p[(mat * 4 + 3) * 65536 + r];
    float4 s = {a.x + b.x + c.x + d.x, a.y + b.y + c.y + d.y,
                a.z + b.z + c.z + d.z, a.w + b.w + c.w + d.w};
    float4* o = (mat == 0) ? (float4*)g_Q : (mat == 1) ? (float4*)g_K : (float4*)g_V;
    o[r] = s;
}

// reduce 4 out partials -> d_out.  grid 256 x 256
__global__ void __launch_bounds__(256) reduce_out(float* __restrict__ out)
{
    const int r = blockIdx.x * 256 + threadIdx.x;     // 0 .. 65535
    const float4* p = (const float4*)g_outp;
    float4 s = {0.f, 0.f, 0.f, 0.f};
#pragma unroll
    for (int k = 0; k < 4; k++) {
        float4 v = p[k * 65536 + r];
        s.x += v.x; s.y += v.y; s.z += v.z; s.w += v.w;
    }
    ((float4*)out)[r] = s;
}

// ---------------------------------------------------------------------------
// Fused attention: block = (32 query rows, 1 head), 256 threads.
// smem floats:
//   ScT [512*33]   scores ScT[j*33 + r]  (stride 33: conflict-free col reads)
//   Q4  [16*33] f4 Q4[d4*33 + r] (phase 1 only)
//   KV  [34816]    phase1: K4[d4*513 + col] f4; phase3: V4[j*17 + c4] f4
//   L   [32*52] u32  compacted top-k lists: (w*inv mantissa-hi23) | idx9
// ---------------------------------------------------------------------------
#define SCT_OFF 0
#define Q4_OFF  (512 * 33)                 // 16896
#define KV_OFF  (Q4_OFF + 16 * 33 * 4)     // 19008
#define L_OFF   (KV_OFF + 34816)           // 53824
#define ATTN_SMEM_BYTES ((L_OFF + 32 * 52) * 4)

__global__ void __launch_bounds__(256, 1) attn_kernel()
{
    extern __shared__ float sm[];
    float*    ScT = sm + SCT_OFF;
    float4*   Q4  = (float4*)(sm + Q4_OFF);
    float4*   KV4 = (float4*)(sm + KV_OFF);
    float*    Vf  = sm + KV_OFF;           // phase-3 scalar view (stride 68)
    uint32_t* L   = (uint32_t*)(sm + L_OFF);

    const int h    = blockIdx.y;
    const int row0 = blockIdx.x * ROWS;
    const int t    = threadIdx.x;

    // ---- load Q (f4-over-d) and K (f4-over-d) ----
#pragma unroll
    for (int i = 0; i < 2; i++) {
        const int f = t + (i << 8);
        const int r = f >> 4, d4 = f & 15;
        Q4[d4 * 33 + r] = *(const float4*)&g_Q[(row0 + r) * DMODEL + h * DH + (d4 << 2)];
    }
#pragma unroll
    for (int i = 0; i < 32; i++) {
        const int f = t + (i << 8);
        const int col = f >> 4, d4 = f & 15;
        KV4[d4 * 513 + col] = *(const float4*)&g_K[col * DMODEL + h * DH + (d4 << 2)];
    }
    __syncthreads();

    // ---- phase 1: scores, micro 4 rows (rr+8i) x 16 cols (tc+32cc) ----
    {
        const int rr = t & 7;
        const int tc = t >> 3;
        float acc[4][16] = {};
        for (int d4 = 0; d4 < 16; d4++) {
            float4 q4[4];
#pragma unroll
            for (int i = 0; i < 4; i++) q4[i] = Q4[d4 * 33 + rr + (i << 3)];
#pragma unroll
            for (int cc = 0; cc < 16; cc++) {
                const float4 k4 = KV4[d4 * 513 + tc + (cc << 5)];
#pragma unroll
                for (int i = 0; i < 4; i++) {
                    float s = acc[i][cc];
                    s = fmaf(q4[i].x, k4.x, s);
                    s = fmaf(q4[i].y, k4.y, s);
                    s = fmaf(q4[i].z, k4.z, s);
                    s = fmaf(q4[i].w, k4.w, s);
                    acc[i][cc] = s;
                }
            }
        }
#pragma unroll
        for (int cc = 0; cc < 16; cc++)
#pragma unroll
            for (int i = 0; i < 4; i++)
                ScT[(tc + (cc << 5)) * 33 + rr + (i << 3)] = fabsf(acc[i][cc]) * SCALE;
    }
    __syncthreads();   // scores done; K region + Q4 region dead

    // ---- copy V into KV region (straight float4, V4[j*17 + c4]) ----
#pragma unroll
    for (int i = 0; i < 32; i++) {
        const int f = t + (i << 8);
        const int j = f >> 4, c4 = f & 15;
        KV4[j * 17 + c4] = *(const float4*)&g_V[j * DMODEL + h * DH + (c4 << 2)];
    }

    // ---- phase 2: per-row top-51 -> compacted normalized (w, idx) list ----
    {
        const int warp = t >> 5, lane = t & 31;
        const unsigned ltmask = (1u << lane) - 1u;
        for (int r = warp; r < ROWS; r += 8) {
            float v[16];
            unsigned u[16];
            float ssum = 0.f;
#pragma unroll
            for (int i = 0; i < 16; i++) {
                v[i] = ScT[(lane + 32 * i) * 33 + r];
                u[i] = __float_as_uint(v[i]);
                ssum += v[i];
            }
            // binary search for the 51st-largest bit pattern
            unsigned lo = 0u, hi = 0x7F800000u;
            while (lo < hi) {
                unsigned mid = lo + ((hi - lo + 1u) >> 1);
                int cnt = 0;
#pragma unroll
                for (int i = 0; i < 16; i++) cnt += (u[i] >= mid);
                cnt = __reduce_add_sync(0xffffffffu, cnt);
                if (cnt >= KTOP) lo = mid; else hi = mid - 1u;
            }
            const unsigned T = lo;
            int   cgt  = 0;
            float tsum = 0.f;
#pragma unroll
            for (int i = 0; i < 16; i++)
                if (u[i] > T) { cgt++; tsum += v[i]; }
            cgt = __reduce_add_sync(0xffffffffu, cgt);
#pragma unroll
            for (int o = 16; o; o >>= 1) {
                tsum += __shfl_xor_sync(0xffffffffu, tsum, o);
                ssum += __shfl_xor_sync(0xffffffffu, ssum, o);
            }
            const float Tf = __uint_as_float(T);
            tsum += (float)(KTOP - cgt) * Tf;
            const float inv = 1.0f / (tsum + 1e-8f * (ssum + 1e-8f));

            // deterministic ballot-scan compaction (lane order within chunks)
            uint32_t* Lr = L + r * 52;
            int base = 0;
            int brem = KTOP - cgt;   // tie budget
#pragma unroll
            for (int i = 0; i < 16; i++) {
                const bool gt = (u[i] > T);
                const bool eq = (u[i] == T);
                const unsigned eqm = __ballot_sync(0xffffffffu, eq);
                const bool teq = eq && (__popc(eqm & ltmask) < brem);
                const unsigned selm = __ballot_sync(0xffffffffu, gt || teq);
                if (gt || teq) {
                    const int pos = base + __popc(selm & ltmask);
                    const float w = v[i] * inv;
                    Lr[pos] = (__float_as_uint(w) & ~511u) | (unsigned)(lane + 32 * i);
                }
                base += __popc(selm);
                const int nties = __popc(eqm);
                brem -= (nties < brem) ? nties : brem;
            }
        }
    }
    __syncthreads();   // lists + V tile ready

    // ---- phase 3: gather out[r] = sum_e w_e * V[idx_e]  (warp per row) ----
    {
        const int warp = t >> 5, lane = t & 31;
        for (int r = warp; r < ROWS; r += 8) {
            const uint32_t* Lr = L + r * 52;
            float2 ac0 = {0.f, 0.f}, ac1 = {0.f, 0.f}, ac2 = {0.f, 0.f};
#pragma unroll 3
            for (int e = 0; e < KTOP; e++) {
                const uint32_t bits = Lr[e];
                const int   idx = bits & 511u;
                const float w   = __uint_as_float(bits & ~511u);
                const float2 vv = *(const float2*)&Vf[idx * 68 + (lane << 1)];
                float2& a = (e % 3 == 0) ? ac0 : (e % 3 == 1) ? ac1 : ac2;
                a.x = fmaf(w, vv.x, a.x);
                a.y = fmaf(w, vv.y, a.y);
            }
            float2 o = {ac0.x + ac1.x + ac2.x, ac0.y + ac1.y + ac2.y};
            *(float2*)&g_ctx[(row0 + r) * DMODEL + h * DH + (lane << 1)] = o;
        }
    }
}

// ---------------------------------------------------------------------------
extern "C" void kernel_launch(void* const* d_in, const int* in_sizes, int n_in,
                              void* d_out, int out_size)
{
    const float* x  = (const float*)d_in[0];
    const float* Wq = (const float*)d_in[1];
    const float* Wk = (const float*)d_in[2];
    const float* Wv = (const float*)d_in[3];
    const float* Wo = (const float*)d_in[4];
    float* out = (float*)d_out;

    cudaFuncSetAttribute(qkv_part, cudaFuncAttributeMaxDynamicSharedMemorySize, GEMM_SMEM_BYTES);
    cudaFuncSetAttribute(out_part, cudaFuncAttributeMaxDynamicSharedMemorySize, GEMM_SMEM_BYTES);
    cudaFuncSetAttribute(attn_kernel, cudaFuncAttributeMaxDynamicSharedMemorySize, ATTN_SMEM_BYTES);

    qkv_part<<<dim3(8, 4, 12), 128, GEMM_SMEM_BYTES>>>(x, Wq, Wk, Wv);
    reduce_qkv<<<768, 256>>>();
    attn_kernel<<<dim3(16, 8), 256, ATTN_SMEM_BYTES>>>();
    out_part<<<dim3(8, 4, 4), 128, GEMM_SMEM_BYTES>>>(Wo);
    reduce_out<<<256, 256>>>(out);
}

// round 6
// speedup vs baseline: 1.0419x; 1.0419x over previous
#include <cuda_runtime.h>
#include <cstdint>

#define NSEQ 512
#define DMODEL 512
#define DH 64
#define NH 8
#define KTOP 51
#define ROWS 32
#define SCALE 2.8284271247461903f   // dh^0.25

// scratch (allocation-free rule: __device__ globals)
__device__ float g_Q[NSEQ * DMODEL];
__device__ float g_K[NSEQ * DMODEL];
__device__ float g_V[NSEQ * DMODEL];
__device__ float g_ctx[NSEQ * DMODEL];
__device__ float g_qkvp[12 * NSEQ * DMODEL];  // qkv split-K partials (3 mats x 4 slices)
__device__ float g_outp[8 * NSEQ * DMODEL];   // out split-K partials (8 slices)

// ---------------------------------------------------------------------------
// cp.async helpers
// ---------------------------------------------------------------------------
__device__ __forceinline__ void cp16(uint32_t dst, const void* src) {
    asm volatile("cp.async.cg.shared.global [%0], [%1], 16;" :: "r"(dst), "l"(src));
}
__device__ __forceinline__ void cp_commit() { asm volatile("cp.async.commit_group;"); }
__device__ __forceinline__ void cp_wait1()  { asm volatile("cp.async.wait_group 1;"); }
__device__ __forceinline__ void cp_wait0()  { asm volatile("cp.async.wait_group 0;"); }

// ---------------------------------------------------------------------------
// GEMM partial: Cp(128x64 tile) = A[m, kbase:kbase+32*kiters] * B^T
// 128 threads, micro 8x8, k-in-float4 smem layout, cp.async double buffer.
// __launch_bounds__(128,3) caps regs (~170) so 3 CTAs co-reside per SM.
// ---------------------------------------------------------------------------
#define GEMM_SMEM_F4 (2 * 8 * 129 + 2 * 8 * 65)
#define GEMM_SMEM_BYTES (GEMM_SMEM_F4 * 16)

__device__ __forceinline__ void gemm128x64(const float* __restrict__ A,
                                           const float* __restrict__ B,
                                           float* __restrict__ Cp,
                                           int kbase, int kiters)
{
    extern __shared__ float4 gsm4[];
    float4* As4 = gsm4;                 // [buf][kq*129 + m]
    float4* Bs4 = gsm4 + 2 * 8 * 129;   // [buf][kq*65 + n]
    const int t  = threadIdx.x;
    const int mr = t & 15;              // rows mr + 16*i
    const int ng = t >> 4;              // cols ng + 8*j
    const int m0 = blockIdx.y * 128;
    const int n0 = blockIdx.x * 64;

    const uint32_t sA = (uint32_t)__cvta_generic_to_shared(As4);
    const uint32_t sB = (uint32_t)__cvta_generic_to_shared(Bs4);

    auto issue = [&](int kit, int buf) {
        const int k0 = kbase + (kit << 5);
#pragma unroll
        for (int i = 0; i < 8; i++) {
            const int f = t + (i << 7);
            const int m = f >> 3, kq = f & 7;
            cp16(sA + (uint32_t)((buf * 1032 + kq * 129 + m) << 4),
                 &A[(m0 + m) * 512 + k0 + (kq << 2)]);
        }
#pragma unroll
        for (int i = 0; i < 4; i++) {
            const int f = t + (i << 7);
            const int n = f >> 3, kq = f & 7;
            cp16(sB + (uint32_t)((buf * 520 + kq * 65 + n) << 4),
                 &B[(n0 + n) * 512 + k0 + (kq << 2)]);
        }
        cp_commit();
    };

    float acc[8][8] = {};
    issue(0, 0);
    for (int kit = 0; kit < kiters; kit++) {
        const int buf = kit & 1;
        if (kit + 1 < kiters) { issue(kit + 1, buf ^ 1); cp_wait1(); }
        else                  { cp_wait0(); }
        __syncthreads();
        const float4* Ab = As4 + buf * 1032;
        const float4* Bb = Bs4 + buf * 520;
#pragma unroll
        for (int kq = 0; kq < 8; kq++) {
            float4 a4[8], b4[8];
#pragma unroll
            for (int i = 0; i < 8; i++) a4[i] = Ab[kq * 129 + mr + (i << 4)];
#pragma unroll
            for (int j = 0; j < 8; j++) b4[j] = Bb[kq * 65 + ng + (j << 3)];
#pragma unroll
            for (int i = 0; i < 8; i++)
#pragma unroll
                for (int j = 0; j < 8; j++) {
                    acc[i][j] = fmaf(a4[i].x, b4[j].x, acc[i][j]);
                    acc[i][j] = fmaf(a4[i].y, b4[j].y, acc[i][j]);
                    acc[i][j] = fmaf(a4[i].z, b4[j].z, acc[i][j]);
                    acc[i][j] = fmaf(a4[i].w, b4[j].w, acc[i][j]);
                }
        }
        __syncthreads();
    }

    // stage outputs through smem for coalesced STG.128
    float* Cs = (float*)gsm4;
#pragma unroll
    for (int i = 0; i < 8; i++)
#pragma unroll
        for (int j = 0; j < 8; j++)
            Cs[(mr + (i << 4)) * 68 + ng + (j << 3)] = acc[i][j];
    __syncthreads();
#pragma unroll
    for (int i = 0; i < 16; i++) {
        const int f = t + (i << 7);
        const int m = f >> 4, q = f & 15;
        *(float4*)&Cp[(m0 + m) * 512 + n0 + (q << 2)] =
            *(const float4*)&Cs[m * 68 + (q << 2)];
    }
}

// qkv partials: grid (8, 4, 12); z = mat*4 + kslice (K=128 per slice)
__global__ void __launch_bounds__(128, 3) qkv_part(const float* __restrict__ X,
                                                   const float* __restrict__ Wq,
                                                   const float* __restrict__ Wk,
                                                   const float* __restrict__ Wv)
{
    const int z = blockIdx.z;
    const int mat = z >> 2, ks = z & 3;
    const float* B = (mat == 0) ? Wq : (mat == 1) ? Wk : Wv;
    gemm128x64(X, B, g_qkvp + z * (NSEQ * DMODEL), ks << 7, 4);
}

// out partials: grid (8, 4, 8); z = kslice (K=64 per slice)
__global__ void __launch_bounds__(128, 3) out_part(const float* __restrict__ Wo)
{
    const int ks = blockIdx.z;
    gemm128x64(g_ctx, Wo, g_outp + ks * (NSEQ * DMODEL), ks << 6, 2);
}

// reduce 4 qkv partials -> g_Q/g_K/g_V.  grid 768 x 256 (f4 granularity)
__global__ void __launch_bounds__(256) reduce_qkv()
{
    const int idx = blockIdx.x * 256 + threadIdx.x;   // 0 .. 196607
    const int mat = idx >> 16, r = idx & 0xFFFF;
    const float4* p = (const float4*)g_qkvp;
    float4 a = p[(mat * 4 + 0) * 65536 + r];
    float4 b = p[(mat * 4 + 1) * 65536 + r];
    float4 c = p[(mat * 4 + 2) * 65536 + r];
    float4 d = p[(mat * 4 + 3) * 65536 + r];
    float4 s = {a.x + b.x + c.x + d.x, a.y + b.y + c.y + d.y,
                a.z + b.z + c.z + d.z, a.w + b.w + c.w + d.w};
    float4* o = (mat == 0) ? (float4*)g_Q : (mat == 1) ? (float4*)g_K : (float4*)g_V;
    o[r] = s;
}

// reduce 8 out partials -> d_out.  grid 256 x 256
__global__ void __launch_bounds__(256) reduce_out(float* __restrict__ out)
{
    const int r = blockIdx.x * 256 + threadIdx.x;     // 0 .. 65535
    const float4* p = (const float4*)g_outp;
    float4 s = {0.f, 0.f, 0.f, 0.f};
#pragma unroll
    for (int k = 0; k < 8; k++) {
        float4 v = p[k * 65536 + r];
        s.x += v.x; s.y += v.y; s.z += v.z; s.w += v.w;
    }
    ((float4*)out)[r] = s;
}

// ---------------------------------------------------------------------------
// Fused attention: block = (32 query rows, 1 head), 256 threads.
// smem floats:
//   ScT [512*33]   scores ScT[j*33 + r]  (stride 33: conflict-free col reads)
//   Q4  [16*33] f4 Q4[d4*33 + r] (phase 1 only)
//   KV  [34816]    phase1: K4[d4*513 + col] f4; phase3: V4[j*17 + c4] f4
//   L   [32*52] u32  compacted top-k lists: (w*inv mantissa-hi23) | idx9
// ---------------------------------------------------------------------------
#define SCT_OFF 0
#define Q4_OFF  (512 * 33)                 // 16896
#define KV_OFF  (Q4_OFF + 16 * 33 * 4)     // 19008
#define L_OFF   (KV_OFF + 34816)           // 53824
#define ATTN_SMEM_BYTES ((L_OFF + 32 * 52) * 4)

__global__ void __launch_bounds__(256, 1) attn_kernel()
{
    extern __shared__ float sm[];
    float*    ScT = sm + SCT_OFF;
    float4*   Q4  = (float4*)(sm + Q4_OFF);
    float4*   KV4 = (float4*)(sm + KV_OFF);
    float*    Vf  = sm + KV_OFF;           // phase-3 scalar view (stride 68)
    uint32_t* L   = (uint32_t*)(sm + L_OFF);

    const int h    = blockIdx.y;
    const int row0 = blockIdx.x * ROWS;
    const int t    = threadIdx.x;

    // ---- load Q (f4-over-d) and K (f4-over-d) ----
#pragma unroll
    for (int i = 0; i < 2; i++) {
        const int f = t + (i << 8);
        const int r = f >> 4, d4 = f & 15;
        Q4[d4 * 33 + r] = *(const float4*)&g_Q[(row0 + r) * DMODEL + h * DH + (d4 << 2)];
    }
#pragma unroll
    for (int i = 0; i < 32; i++) {
        const int f = t + (i << 8);
        const int col = f >> 4, d4 = f & 15;
        KV4[d4 * 513 + col] = *(const float4*)&g_K[col * DMODEL + h * DH + (d4 << 2)];
    }
    __syncthreads();

    // ---- phase 1: scores, micro 4 rows (rr+8i) x 16 cols (tc+32cc) ----
    {
        const int rr = t & 7;
        const int tc = t >> 3;
        float acc[4][16] = {};
        for (int d4 = 0; d4 < 16; d4++) {
            float4 q4[4];
#pragma unroll
            for (int i = 0; i < 4; i++) q4[i] = Q4[d4 * 33 + rr + (i << 3)];
#pragma unroll
            for (int cc = 0; cc < 16; cc++) {
                const float4 k4 = KV4[d4 * 513 + tc + (cc << 5)];
#pragma unroll
                for (int i = 0; i < 4; i++) {
                    float s = acc[i][cc];
                    s = fmaf(q4[i].x, k4.x, s);
                    s = fmaf(q4[i].y, k4.y, s);
                    s = fmaf(q4[i].z, k4.z, s);
                    s = fmaf(q4[i].w, k4.w, s);
                    acc[i][cc] = s;
                }
            }
        }
#pragma unroll
        for (int cc = 0; cc < 16; cc++)
#pragma unroll
            for (int i = 0; i < 4; i++)
                ScT[(tc + (cc << 5)) * 33 + rr + (i << 3)] = fabsf(acc[i][cc]) * SCALE;
    }
    __syncthreads();   // scores done; K region + Q4 region dead

    // ---- copy V into KV region (straight float4, V4[j*17 + c4]) ----
#pragma unroll
    for (int i = 0; i < 32; i++) {
        const int f = t + (i << 8);
        const int j = f >> 4, c4 = f & 15;
        KV4[j * 17 + c4] = *(const float4*)&g_V[j * DMODEL + h * DH + (c4 << 2)];
    }

    // ---- phase 2: per-row top-51 -> compacted normalized (w, idx) list ----
    {
        const int warp = t >> 5, lane = t & 31;
        const unsigned ltmask = (1u << lane) - 1u;
        for (int r = warp; r < ROWS; r += 8) {
            float v[16];
            unsigned u[16];
            float ssum = 0.f;
#pragma unroll
            for (int i = 0; i < 16; i++) {
                v[i] = ScT[(lane + 32 * i) * 33 + r];
                u[i] = __float_as_uint(v[i]);
                ssum += v[i];
            }
            // binary search for the 51st-largest bit pattern
            unsigned lo = 0u, hi = 0x7F800000u;
            while (lo < hi) {
                unsigned mid = lo + ((hi - lo + 1u) >> 1);
                int cnt = 0;
#pragma unroll
                for (int i = 0; i < 16; i++) cnt += (u[i] >= mid);
                cnt = __reduce_add_sync(0xffffffffu, cnt);
                if (cnt >= KTOP) lo = mid; else hi = mid - 1u;
            }
            const unsigned T = lo;
            int   cgt  = 0;
            float tsum = 0.f;
#pragma unroll
            for (int i = 0; i < 16; i++)
                if (u[i] > T) { cgt++; tsum += v[i]; }
            cgt = __reduce_add_sync(0xffffffffu, cgt);
#pragma unroll
            for (int o = 16; o; o >>= 1) {
                tsum += __shfl_xor_sync(0xffffffffu, tsum, o);
                ssum += __shfl_xor_sync(0xffffffffu, ssum, o);
            }
            const float Tf = __uint_as_float(T);
            tsum += (float)(KTOP - cgt) * Tf;
            const float inv = 1.0f / (tsum + 1e-8f * (ssum + 1e-8f));

            // deterministic ballot-scan compaction (lane order within chunks)
            uint32_t* Lr = L + r * 52;
            int base = 0;
            int brem = KTOP - cgt;   // tie budget
#pragma unroll
            for (int i = 0; i < 16; i++) {
                const bool gt = (u[i] > T);
                const bool eq = (u[i] == T);
                const unsigned eqm = __ballot_sync(0xffffffffu, eq);
                const bool teq = eq && (__popc(eqm & ltmask) < brem);
                const unsigned selm = __ballot_sync(0xffffffffu, gt || teq);
                if (gt || teq) {
                    const int pos = base + __popc(selm & ltmask);
                    const float w = v[i] * inv;
                    Lr[pos] = (__float_as_uint(w) & ~511u) | (unsigned)(lane + 32 * i);
                }
                base += __popc(selm);
                const int nties = __popc(eqm);
                brem -= (nties < brem) ? nties : brem;
            }
        }
    }
    __syncthreads();   // lists + V tile ready

    // ---- phase 3: gather out[r] = sum_e w_e * V[idx_e]  (warp per row) ----
    {
        const int warp = t >> 5, lane = t & 31;
        for (int r = warp; r < ROWS; r += 8) {
            const uint32_t* Lr = L + r * 52;
            float2 ac0 = {0.f, 0.f}, ac1 = {0.f, 0.f}, ac2 = {0.f, 0.f};
#pragma unroll 3
            for (int e = 0; e < KTOP; e++) {
                const uint32_t bits = Lr[e];
                const int   idx = bits & 511u;
                const float w   = __uint_as_float(bits & ~511u);
                const float2 vv = *(const float2*)&Vf[idx * 68 + (lane << 1)];
                float2& a = (e % 3 == 0) ? ac0 : (e % 3 == 1) ? ac1 : ac2;
                a.x = fmaf(w, vv.x, a.x);
                a.y = fmaf(w, vv.y, a.y);
            }
            float2 o = {ac0.x + ac1.x + ac2.x, ac0.y + ac1.y + ac2.y};
            *(float2*)&g_ctx[(row0 + r) * DMODEL + h * DH + (lane << 1)] = o;
        }
    }
}

// ---------------------------------------------------------------------------
extern "C" void kernel_launch(void* const* d_in, const int* in_sizes, int n_in,
                              void* d_out, int out_size)
{
    const float* x  = (const float*)d_in[0];
    const float* Wq = (const float*)d_in[1];
    const float* Wk = (const float*)d_in[2];
    const float* Wv = (const float*)d_in[3];
    const float* Wo = (const float*)d_in[4];
    float* out = (float*)d_out;

    cudaFuncSetAttribute(qkv_part, cudaFuncAttributeMaxDynamicSharedMemorySize, GEMM_SMEM_BYTES);
    cudaFuncSetAttribute(out_part, cudaFuncAttributeMaxDynamicSharedMemorySize, GEMM_SMEM_BYTES);
    cudaFuncSetAttribute(attn_kernel, cudaFuncAttributeMaxDynamicSharedMemorySize, ATTN_SMEM_BYTES);

    qkv_part<<<dim3(8, 4, 12), 128, GEMM_SMEM_BYTES>>>(x, Wq, Wk, Wv);
    reduce_qkv<<<768, 256>>>();
    attn_kernel<<<dim3(16, 8), 256, ATTN_SMEM_BYTES>>>();
    out_part<<<dim3(8, 4, 8), 128, GEMM_SMEM_BYTES>>>(Wo);
    reduce_out<<<256, 256>>>(out);
}